// round 1
// baseline (speedup 1.0000x reference)
#include <cuda_runtime.h>

#define CH 256     // B*C channels
#define HH 251
#define WW 509
#define HP 256
#define WP 512
#define ROWS 4
#define WPAD (WP + 3)   // 515-float2 row stride to soften smem bank conflicts

// scratch: per channel a WPxHP complex grid, stored w-major: A[c][w][h]
__device__ float2 g_A[CH * WP * HP];   // 256 MB

__device__ __forceinline__ float2 cmul(float2 a, float2 b) {
    return make_float2(fmaf(a.x, b.x, -a.y * b.y),
                       fmaf(a.x, b.y,  a.y * b.x));
}

// Stockham radix-2 autosort FFT, one warp per transform, smem ping-pong.
// Data starts in `a`. For LOG2N=9 result ends in `b`; for LOG2N=8 in `a`.
template<int LOG2N, bool INV>
__device__ __forceinline__ void warp_fft(float2* a, float2* b,
                                         const float2* tw, int lane) {
    const int NB = 1 << (LOG2N - 1);
    float2* src = a;
    float2* dst = b;
    __syncwarp();
    #pragma unroll
    for (int t = 0; t < LOG2N; ++t) {
        const int s = 1 << t;
        #pragma unroll
        for (int r = 0; r < NB / 32; ++r) {
            int i = lane + 32 * r;
            int j = i & ~(s - 1);          // = p<<t, twiddle index W_N^j
            float2 x = src[i];
            float2 y = src[i + NB];
            float2 w = tw[j];
            if (INV) w.y = -w.y;
            dst[i + j]     = make_float2(x.x + y.x, x.y + y.y);
            float2 d       = make_float2(x.x - y.x, x.y - y.y);
            dst[i + j + s] = cmul(d, w);
        }
        __syncwarp();
        float2* tmp = src; src = dst; dst = tmp;
    }
}

// K1: rows. z = u + i*k (zero padded), FFT-512 per row, transposed store.
__global__ void __launch_bounds__(128) fftconv_k1(const float* __restrict__ u,
                                                  const float* __restrict__ kk) {
    __shared__ float2 bufA[ROWS][WPAD];
    __shared__ float2 bufB[ROWS][WPAD];
    __shared__ float2 tw[WP / 2];
    const int tid = threadIdx.x;
    const int lane = tid & 31, wid = tid >> 5;
    const int c = blockIdx.y;
    const int h0 = blockIdx.x * ROWS;

    for (int j = tid; j < WP / 2; j += 128) {
        float sn, cn;
        __sincosf(-6.28318530717958647f * j / WP, &sn, &cn);
        tw[j] = make_float2(cn, sn);
    }
    #pragma unroll
    for (int q = 0; q < ROWS * WP / 128; ++q) {
        int idx = tid + 128 * q;
        int r = idx >> 9, w = idx & (WP - 1);
        int h = h0 + r;
        float ur = 0.f, kr = 0.f;
        if (h < HH && w < WW) {
            int g = (c * HH + h) * WW + w;
            ur = u[g];
            kr = kk[g];
        }
        bufA[r][w] = make_float2(ur, kr);
    }
    __syncthreads();
    warp_fft<9, false>(bufA[wid], bufB[wid], tw, lane);   // result in bufB
    __syncthreads();
    float2* out = g_A + (size_t)c * (WP * HP) + h0;
    #pragma unroll
    for (int q = 0; q < ROWS * WP / 128; ++q) {
        int idx = tid + 128 * q;
        int r = idx & (ROWS - 1), w = idx >> 2;
        out[w * HP + r] = bufB[r][w];   // 32B-chunk coalesced transposed store
    }
}

// K2: column pair (w, 512-w): FFT-256, Hermitian split U,K, P=U*K, IFFT-256.
__global__ void __launch_bounds__(64) fftconv_k2() {
    __shared__ float2 colA[2][HP];
    __shared__ float2 colB[2][HP];
    __shared__ float2 tw[HP / 2];
    const int tid = threadIdx.x;
    const int lane = tid & 31, wp = tid >> 5;
    const int w = blockIdx.x;                 // 0..256
    const int c = blockIdx.y;
    const int w2 = (WP - w) & (WP - 1);
    const int mycol = wp ? w2 : w;

    for (int j = tid; j < HP / 2; j += 64) {
        float sn, cn;
        __sincosf(-6.28318530717958647f * j / HP, &sn, &cn);
        tw[j] = make_float2(cn, sn);
    }
    float2* g = g_A + (size_t)c * (WP * HP) + (size_t)mycol * HP;
    #pragma unroll
    for (int r = 0; r < HP / 32; ++r)
        colA[wp][lane + 32 * r] = g[lane + 32 * r];
    __syncthreads();                                   // data + twiddles ready
    warp_fft<8, false>(colA[wp], colB[wp], tw, lane);  // result in colA
    __syncthreads();                                   // peer column visible

    float2 pv[HP / 32];
    #pragma unroll
    for (int r = 0; r < HP / 32; ++r) {
        int hh = lane + 32 * r;
        int hm = (HP - hh) & (HP - 1);
        float2 z1 = colA[wp][hh];           // Z(h, w_self)
        float2 z2 = colA[wp ^ 1][hm];       // Z(-h, -w_self)
        // U = (Z + conj(Z-))/2 ; K = (Z - conj(Z-))/(2i)
        float2 uf = make_float2(0.5f * (z1.x + z2.x),  0.5f * (z1.y - z2.y));
        float2 kf = make_float2(0.5f * (z1.y + z2.y), -0.5f * (z1.x - z2.x));
        pv[r] = cmul(uf, kf);
    }
    __syncthreads();                        // all cross-reads done before overwrite
    #pragma unroll
    for (int r = 0; r < HP / 32; ++r)
        colA[wp][lane + 32 * r] = pv[r];
    warp_fft<8, true>(colA[wp], colB[wp], tw, lane);   // result in colA
    if (!(wp == 1 && w2 == w)) {            // self-paired column: store once
        #pragma unroll
        for (int r = 0; r < HP / 32; ++r)
            g[lane + 32 * r] = colA[wp][lane + 32 * r];
    }
}

// K3: rows. IFFT-512, real part * N^-1.5, cropped store.
__global__ void __launch_bounds__(128) fftconv_k3(float* __restrict__ y) {
    __shared__ float2 bufA[ROWS][WPAD];
    __shared__ float2 bufB[ROWS][WPAD];
    __shared__ float2 tw[WP / 2];
    const int tid = threadIdx.x;
    const int lane = tid & 31, wid = tid >> 5;
    const int c = blockIdx.y;
    const int h0 = blockIdx.x * ROWS;

    for (int j = tid; j < WP / 2; j += 128) {
        float sn, cn;
        __sincosf(-6.28318530717958647f * j / WP, &sn, &cn);
        tw[j] = make_float2(cn, sn);
    }
    const float2* in = g_A + (size_t)c * (WP * HP) + h0;
    #pragma unroll
    for (int q = 0; q < ROWS * WP / 128; ++q) {
        int idx = tid + 128 * q;
        int r = idx & (ROWS - 1), w = idx >> 2;
        bufA[r][w] = in[w * HP + r];
    }
    __syncthreads();
    warp_fft<9, true>(bufA[wid], bufB[wid], tw, lane);   // result in bufB
    __syncthreads();
    const float scale = 2.1073424255447017e-8f;          // 131072^-1.5 = 2^-25.5
    #pragma unroll
    for (int q = 0; q < ROWS * WP / 128; ++q) {
        int idx = tid + 128 * q;
        int r = idx >> 9, w = idx & (WP - 1);
        int h = h0 + r;
        if (h < HH && w < WW)
            y[(c * HH + h) * WW + w] = bufB[r][w].x * scale;
    }
}

extern "C" void kernel_launch(void* const* d_in, const int* in_sizes, int n_in,
                              void* d_out, int out_size) {
    const float* u = (const float*)d_in[0];
    const float* k = (const float*)d_in[1];
    float* y = (float*)d_out;

    fftconv_k1<<<dim3(HP / ROWS, CH), 128>>>(u, k);      // 64 x 256 blocks
    fftconv_k2<<<dim3(WP / 2 + 1, CH), 64>>>();          // 257 x 256 blocks
    fftconv_k3<<<dim3(63, CH), 128>>>(y);                // rows 0..250 only
}

// round 2
// speedup vs baseline: 1.6813x; 1.6813x over previous
#include <cuda_runtime.h>

#define CH 256     // B*C channels
#define HH 251
#define WW 509
#define HP 256
#define WP 512
#define ROWS 4

// scratch: per channel a WPxHP complex grid, stored w-major: A[c][w][h]
__device__ __align__(16) float2 g_A[CH * WP * HP];   // 256 MB

__device__ __forceinline__ float2 cmul(float2 a, float2 b) {
    return make_float2(fmaf(a.x, b.x, -a.y * b.y),
                       fmaf(a.x, b.y,  a.y * b.x));
}

__device__ __forceinline__ int rev5(int x) { return (int)(__brev((unsigned)x) >> 27); }

// bit-reverse of a small compile-time-constant index (folds under #pragma unroll)
__device__ __forceinline__ int crev(int x, int bits) {
    int r = 0;
    #pragma unroll
    for (int i = 0; i < 5; ++i)
        if (i < bits) r |= ((x >> i) & 1) << (bits - 1 - i);
    return r;
}

// 32-point DIF FFT across lanes via shfl_xor. One per register slot.
// Input: lane l holds sequence element l. Output: lane l holds X[rev5(l)].
template<int NR, bool INV>
__device__ __forceinline__ void lane_fft(float2* v, int lane) {
    float2 w;  // stage twiddle W32^{+/- e}, e = (lane&15) initially
    {
        float ang = (INV ? 0.19634954084936207f : -0.19634954084936207f) * (float)(lane & 15);
        __sincosf(ang, &w.y, &w.x);
    }
    #pragma unroll
    for (int m = 16; m >= 1; m >>= 1) {
        const bool up = (lane & m) != 0;
        #pragma unroll
        for (int r = 0; r < NR; ++r) {
            float2 p;
            p.x = __shfl_xor_sync(0xffffffffu, v[r].x, m);
            p.y = __shfl_xor_sync(0xffffffffu, v[r].y, m);
            float2 s;
            if (up) {
                s = make_float2(p.x - v[r].x, p.y - v[r].y);
                s = cmul(s, w);
            } else {
                s = make_float2(v[r].x + p.x, v[r].y + p.y);
            }
            v[r] = s;
        }
        if (m > 1) {
            // next stage twiddle: square, with sign fix for wrapped exponent
            w = cmul(w, w);
            if (lane & (m >> 1)) { w.x = -w.x; w.y = -w.y; }
        }
    }
}

// NR-point DIF FFT in registers, constant twiddles (W16 table covers NR=8,16).
// Output slot r holds X[crev(r, log2(NR))].
template<int NR, bool INV>
__device__ __forceinline__ void reg_fft(float2* v) {
    const float C[8] = { 1.f,  0.9238795325112867f,  0.7071067811865476f,  0.3826834323650898f,
                         0.f, -0.3826834323650898f, -0.7071067811865476f, -0.9238795325112867f};
    const float S[8] = { 0.f, -0.3826834323650898f, -0.7071067811865476f, -0.9238795325112867f,
                        -1.f, -0.9238795325112867f, -0.7071067811865476f, -0.3826834323650898f};
    #pragma unroll
    for (int m = NR / 2; m >= 1; m >>= 1) {
        #pragma unroll
        for (int b = 0; b < NR; b += 2 * m) {
            #pragma unroll
            for (int i = 0; i < m; ++i) {
                float2 lo = v[b + i], hi = v[b + i + m];
                v[b + i] = make_float2(lo.x + hi.x, lo.y + hi.y);
                float2 d = make_float2(lo.x - hi.x, lo.y - hi.y);
                const int j = i * (8 / m);
                if (j == 0) {
                    v[b + i + m] = d;
                } else {
                    float2 wt = make_float2(C[j], INV ? -S[j] : S[j]);
                    v[b + i + m] = cmul(d, wt);
                }
            }
        }
    }
}

// mid twiddle: v[r] *= W_N^{+/- r*k2}, k2 per-lane
template<int NR, bool INV>
__device__ __forceinline__ void twiddle_mid(float2* v, int k2, float twoPiOverN) {
    float ang = (INV ? twoPiOverN : -twoPiOverN) * (float)k2;
    float2 wb; __sincosf(ang, &wb.y, &wb.x);
    float2 w = wb;
    #pragma unroll
    for (int r = 1; r < NR; ++r) {
        v[r] = cmul(v[r], w);
        w = cmul(w, wb);
    }
}

#define SW9(i) ((i) ^ (((i) >> 4) & 15))   // swizzle for 512-entry float2 buffers
#define SW8(i) ((i) ^ (((i) >> 4) & 7))    // swizzle for 256-entry float2 buffers

// K1: rows. z = u + i*k (zero padded), FFT-512 per row, transposed store.
__global__ void __launch_bounds__(128) fftconv_k1(const float* __restrict__ u,
                                                  const float* __restrict__ kk) {
    __shared__ float2 buf[ROWS][520];
    const int tid = threadIdx.x;
    const int lane = tid & 31, wid = tid >> 5;
    const int c = blockIdx.y;
    const int h = blockIdx.x * ROWS + wid;

    float2 v[16];
    if (h < HH) {
        const float* pu = u + (size_t)(c * HH + h) * WW;
        const float* pk = kk + (size_t)(c * HH + h) * WW;
        const int base = lane * 16;
        #pragma unroll
        for (int r = 0; r < 16; ++r) {
            int n = base + r;
            bool ok = n < WW;
            v[r].x = ok ? pu[n] : 0.f;
            v[r].y = ok ? pk[n] : 0.f;
        }
    } else {
        #pragma unroll
        for (int r = 0; r < 16; ++r) v[r] = make_float2(0.f, 0.f);
    }

    lane_fft<16, false>(v, lane);
    const int k2 = rev5(lane);
    twiddle_mid<16, false>(v, k2, 0.012271846303085130f);  // 2*pi/512
    reg_fft<16, false>(v);

    #pragma unroll
    for (int r = 0; r < 16; ++r) {
        int k = k2 + 32 * crev(r, 4);
        buf[wid][SW9(k)] = v[r];
    }
    __syncthreads();

    float2* out = g_A + (size_t)c * (WP * HP) + blockIdx.x * ROWS;
    #pragma unroll
    for (int q = 0; q < ROWS * WP / 128; ++q) {
        int idx = tid + 128 * q;
        int rr = idx & 3, w = idx >> 2;
        out[w * HP + rr] = buf[rr][SW9(w)];   // coalesced transposed store
    }
}

// K2: column pair (w, 512-w): FFT-256, Hermitian split U,K, P=U*K, IFFT-256.
__global__ void __launch_bounds__(64) fftconv_k2() {
    __shared__ float2 colZ[2][256];
    const int tid = threadIdx.x;
    const int lane = tid & 31, wp = tid >> 5;
    const int w = blockIdx.x;                 // 0..256
    const int c = blockIdx.y;
    const int w2 = (WP - w) & (WP - 1);
    const int mycol = wp ? w2 : w;

    float2* g = g_A + (size_t)c * (WP * HP) + (size_t)mycol * HP;

    float2 v[8];
    const float4* p4 = (const float4*)(g + lane * 8);   // 64B-aligned
    #pragma unroll
    for (int r = 0; r < 4; ++r) {
        float4 t = p4[r];
        v[2 * r]     = make_float2(t.x, t.y);
        v[2 * r + 1] = make_float2(t.z, t.w);
    }

    lane_fft<8, false>(v, lane);
    const int k2v = rev5(lane);
    twiddle_mid<8, false>(v, k2v, 0.024543692606170260f);  // 2*pi/256
    reg_fft<8, false>(v);

    #pragma unroll
    for (int r = 0; r < 8; ++r) {
        int k = k2v + 32 * crev(r, 3);
        colZ[wp][SW8(k)] = v[r];
    }
    __syncthreads();

    float2 pv[8];
    #pragma unroll
    for (int r = 0; r < 8; ++r) {
        int k = k2v + 32 * crev(r, 3);
        int km = (HP - k) & (HP - 1);
        float2 z1 = v[r];                       // Z(k, w_self)
        float2 z2 = colZ[wp ^ 1][SW8(km)];      // Z(-k, -w_self)
        float2 uf = make_float2(0.5f * (z1.x + z2.x),  0.5f * (z1.y - z2.y));
        float2 kf = make_float2(0.5f * (z1.y + z2.y), -0.5f * (z1.x - z2.x));
        pv[r] = cmul(uf, kf);
    }
    __syncthreads();                            // cross-reads done before overwrite
    #pragma unroll
    for (int r = 0; r < 8; ++r) {
        int k = k2v + 32 * crev(r, 3);
        colZ[wp][SW8(k)] = pv[r];
    }
    __syncthreads();
    #pragma unroll
    for (int r = 0; r < 8; ++r) {
        int m = lane * 8 + r;                   // natural-order input for inverse
        v[r] = colZ[wp][SW8(m)];
    }

    lane_fft<8, true>(v, lane);
    twiddle_mid<8, true>(v, k2v, 0.024543692606170260f);
    reg_fft<8, true>(v);

    if (!(wp == 1 && w2 == w)) {                // self-paired column: store once
        #pragma unroll
        for (int r = 0; r < 8; ++r)
            g[k2v + 32 * crev(r, 3)] = v[r];
    }
}

// K3: rows. IFFT-512, real part * N^-1.5, cropped store.
__global__ void __launch_bounds__(128) fftconv_k3(float* __restrict__ y) {
    __shared__ float2 buf[ROWS][520];
    const int tid = threadIdx.x;
    const int lane = tid & 31, wid = tid >> 5;
    const int c = blockIdx.y;
    const int h0 = blockIdx.x * ROWS;
    const int h = h0 + wid;

    const float2* in = g_A + (size_t)c * (WP * HP) + h0;
    #pragma unroll
    for (int q = 0; q < ROWS * WP / 128; ++q) {
        int idx = tid + 128 * q;
        int rr = idx & 3, w = idx >> 2;
        buf[rr][SW9(w)] = in[w * HP + rr];      // coalesced transposed load
    }
    __syncthreads();

    float2 v[16];
    #pragma unroll
    for (int r = 0; r < 16; ++r) {
        int m = lane * 16 + r;                  // natural-order input for inverse
        v[r] = buf[wid][SW9(m)];
    }

    lane_fft<16, true>(v, lane);
    const int k2 = rev5(lane);
    twiddle_mid<16, true>(v, k2, 0.012271846303085130f);
    reg_fft<16, true>(v);

    if (h < HH) {
        const float scale = 2.1073424255447017e-8f;  // 131072^-1.5 = 2^-25.5
        float* py = y + (size_t)(c * HH + h) * WW;
        #pragma unroll
        for (int r = 0; r < 16; ++r) {
            int n = k2 + 32 * crev(r, 4);
            if (n < WW) py[n] = v[r].x * scale;
        }
    }
}

extern "C" void kernel_launch(void* const* d_in, const int* in_sizes, int n_in,
                              void* d_out, int out_size) {
    const float* u = (const float*)d_in[0];
    const float* k = (const float*)d_in[1];
    float* y = (float*)d_out;

    fftconv_k1<<<dim3(HP / ROWS, CH), 128>>>(u, k);      // 64 x 256 blocks
    fftconv_k2<<<dim3(WP / 2 + 1, CH), 64>>>();          // 257 x 256 blocks
    fftconv_k3<<<dim3(63, CH), 128>>>(y);                // rows 0..250 only
}

// round 3
// speedup vs baseline: 2.4747x; 1.4718x over previous
#include <cuda_runtime.h>

#define CH 256     // B*C channels
#define HH 251
#define WW 509
#define HP 256
#define WP 512

// scratch: per channel a WPxHP complex grid, stored w-major: A[c][w][h]
__device__ __align__(16) float2 g_A[CH * WP * HP];   // 256 MB

__device__ __forceinline__ float2 cmul(float2 a, float2 b) {
    return make_float2(fmaf(a.x, b.x, -a.y * b.y),
                       fmaf(a.x, b.y,  a.y * b.x));
}

// bit-reverse of a compile-time-constant index (folds under #pragma unroll)
__device__ __forceinline__ int crev(int x, int bits) {
    int r = 0;
    #pragma unroll
    for (int i = 0; i < 5; ++i)
        if (i < bits) r |= ((x >> i) & 1) << (bits - 1 - i);
    return r;
}

// 16-point DIF FFT in registers. Input natural order; output v[r] = X[crev(r,4)].
template<bool INV>
__device__ __forceinline__ void reg_fft16(float2* v) {
    const float C[8] = { 1.f,  0.9238795325112867f,  0.7071067811865476f,  0.3826834323650898f,
                         0.f, -0.3826834323650898f, -0.7071067811865476f, -0.9238795325112867f};
    const float S[8] = { 0.f, -0.3826834323650898f, -0.7071067811865476f, -0.9238795325112867f,
                        -1.f, -0.9238795325112867f, -0.7071067811865476f, -0.3826834323650898f};
    #pragma unroll
    for (int m = 8; m >= 1; m >>= 1) {
        #pragma unroll
        for (int b = 0; b < 16; b += 2 * m) {
            #pragma unroll
            for (int i = 0; i < m; ++i) {
                float2 lo = v[b + i], hi = v[b + i + m];
                v[b + i] = make_float2(lo.x + hi.x, lo.y + hi.y);
                float2 d = make_float2(lo.x - hi.x, lo.y - hi.y);
                const int j = i * (8 / m);
                if (j == 0) {
                    v[b + i + m] = d;
                } else {
                    float2 wt = make_float2(C[j], INV ? -S[j] : S[j]);
                    v[b + i + m] = cmul(d, wt);
                }
            }
        }
    }
}

// twiddle: v[slot holding k1=c] *= W_N^{+/- t*c}, iterated in natural c order.
template<bool INV>
__device__ __forceinline__ void twiddle16_nat(float2* v, int t, float twoPiOverN) {
    float ang = (INV ? twoPiOverN : -twoPiOverN) * (float)t;
    float2 wb; __sincosf(ang, &wb.y, &wb.x);
    float2 w = wb;
    #pragma unroll
    for (int c = 1; c < 16; ++c) {
        v[crev(c, 4)] = cmul(v[crev(c, 4)], w);
        w = cmul(w, wb);
    }
}

// K1: rows. z = u + i*k (zero padded), FFT-512 per row (16reg x [16reg x 2]),
// transposed store to g_A. One warp per row, 4 rows per block.
__global__ void __launch_bounds__(128) fftconv_k1(const float* __restrict__ u,
                                                  const float* __restrict__ kk) {
    __shared__ float2 S[4][16][33];     // per-warp 16x32(+pad) transpose
    __shared__ float2 buf[4][512];      // 4-row staging for transposed STG
    const int tid = threadIdx.x;
    const int lane = tid & 31, wid = tid >> 5;
    const int c = blockIdx.y;
    const int h = blockIdx.x * 4 + wid;

    float2 v[16];
    if (h < HH) {
        const float* pu = u + (size_t)(c * HH + h) * WW;
        const float* pk = kk + (size_t)(c * HH + h) * WW;
        #pragma unroll
        for (int s = 0; s < 16; ++s) {
            int n = lane + 32 * s;
            bool ok = n < WW;
            v[s].x = ok ? pu[n] : 0.f;
            v[s].y = ok ? pk[n] : 0.f;
        }
    } else {
        #pragma unroll
        for (int s = 0; s < 16; ++s) v[s] = make_float2(0.f, 0.f);
    }

    reg_fft16<false>(v);                               // A_t[k1], k1=crev(r)
    twiddle16_nat<false>(v, lane, 0.012271846303085130f);  // * W512^{t*k1}
    #pragma unroll
    for (int r = 0; r < 16; ++r) S[wid][crev(r, 4)][lane] = v[r];
    __syncwarp();

    // FFT-32 over t: fold t=a+16b (smem broadcast), then reg FFT-16 over a
    const int k1 = lane & 15, k2 = lane >> 4;
    {
        float2 w = make_float2(1.f, 0.f), wq;
        __sincosf(-0.19634954084936207f * (float)k2, &wq.y, &wq.x);  // W32^{k2}
        const float sgn = k2 ? -1.f : 1.f;
        #pragma unroll
        for (int a = 0; a < 16; ++a) {
            float2 L0 = S[wid][k1][a];
            float2 L1 = S[wid][k1][a + 16];
            float2 hh = make_float2(L0.x + sgn * L1.x, L0.y + sgn * L1.y);
            v[a] = cmul(hh, w);
            w = cmul(w, wq);
        }
    }
    reg_fft16<false>(v);                 // v[r] = X[lane + 32*crev(r)]

    #pragma unroll
    for (int r = 0; r < 16; ++r) {
        int k = lane + 32 * crev(r, 4);
        buf[wid][k ^ (8 * wid)] = v[r];
    }
    __syncthreads();
    float2* out = g_A + (size_t)c * (WP * HP) + blockIdx.x * 4;
    #pragma unroll
    for (int q = 0; q < 16; ++q) {
        int idx = tid + 128 * q;
        int rr = idx & 3, w = idx >> 2;
        out[(size_t)w * HP + rr] = buf[rr][w ^ (8 * rr)];  // 32B-chunk coalesced
    }
}

// K2: column pair (w, 512-w): FFT-256 (16x16, 16 threads/col), Hermitian split,
// P=U*K, IFFT-256. One warp = one pair; 8 warps per block; warp-level syncs only.
__global__ void __launch_bounds__(256) fftconv_k2() {
    __shared__ float2 R[8][2][272];      // per warp/half: 16x17 transpose, aliased colZ
    const int tid = threadIdx.x;
    const int lane = tid & 31, wp = tid >> 5;
    const int half = lane >> 4, tl = lane & 15;
    const int p = blockIdx.x * 8 + wp;
    if (p > 256) return;                 // uniform per warp; no __syncthreads below
    const int w = p, w2 = (WP - w) & (WP - 1);
    const int col = half ? w2 : w;
    const int c = blockIdx.y;
    float2* g = g_A + (size_t)c * (WP * HP) + (size_t)col * HP;
    float2* T    = &R[wp][half][0];      // transpose view: [k1*17 + t]
    float2* Zown = &R[wp][half][0];      // natural-k view: [k]
    float2* Zoth = &R[wp][half ^ 1][0];

    float2 v[16];
    #pragma unroll
    for (int s = 0; s < 16; ++s) v[s] = g[tl + 16 * s];

    reg_fft16<false>(v);
    twiddle16_nat<false>(v, tl, 0.024543692606170260f);    // * W256^{t*k1}
    #pragma unroll
    for (int r = 0; r < 16; ++r) T[crev(r, 4) * 17 + tl] = v[r];
    __syncwarp();
    #pragma unroll
    for (int j = 0; j < 16; ++j) v[j] = T[tl * 17 + j];
    reg_fft16<false>(v);                  // v[r] = X[tl + 16*crev(r)] of col
    __syncwarp();                         // transpose reads done before Z overwrite

    #pragma unroll
    for (int r = 0; r < 16; ++r) Zown[tl + 16 * crev(r, 4)] = v[r];
    __syncwarp();
    #pragma unroll
    for (int r = 0; r < 16; ++r) {
        int k = tl + 16 * crev(r, 4);
        int km = (HP - k) & (HP - 1);
        float2 z1 = v[r];                 // Z(k, w_self)
        float2 z2 = Zoth[km];             // Z(-k, -w_self)
        float2 uf = make_float2(0.5f * (z1.x + z2.x),  0.5f * (z1.y - z2.y));
        float2 kf = make_float2(0.5f * (z1.y + z2.y), -0.5f * (z1.x - z2.x));
        v[r] = cmul(uf, kf);
    }
    __syncwarp();                         // Hermitian reads done before T reuse

    // inverse: P is held exactly as q[tl + 16*s] with s = crev(r) -> relabel
    float2 v2[16];
    #pragma unroll
    for (int r = 0; r < 16; ++r) v2[crev(r, 4)] = v[r];
    reg_fft16<true>(v2);
    twiddle16_nat<true>(v2, tl, 0.024543692606170260f);
    #pragma unroll
    for (int r = 0; r < 16; ++r) T[crev(r, 4) * 17 + tl] = v2[r];
    __syncwarp();
    #pragma unroll
    for (int j = 0; j < 16; ++j) v2[j] = T[tl * 17 + j];
    reg_fft16<true>(v2);                  // y[tl + 16*crev(r)]

    if (!(half == 1 && w2 == w)) {        // self-paired column: store once
        #pragma unroll
        for (int r = 0; r < 16; ++r) g[tl + 16 * crev(r, 4)] = v2[r];
    }
}

// K3: rows. IFFT-512, real part * N^-1.5, cropped coalesced store.
__global__ void __launch_bounds__(128) fftconv_k3(float* __restrict__ y) {
    __shared__ float2 S[4][16][33];
    __shared__ float2 buf[4][512];
    const int tid = threadIdx.x;
    const int lane = tid & 31, wid = tid >> 5;
    const int c = blockIdx.y;
    const int h0 = blockIdx.x * 4;
    const int h = h0 + wid;

    const float2* in = g_A + (size_t)c * (WP * HP) + h0;
    #pragma unroll
    for (int q = 0; q < 16; ++q) {
        int idx = tid + 128 * q;
        int rr = idx & 3, w = idx >> 2;
        buf[rr][w ^ (8 * rr)] = in[(size_t)w * HP + rr];   // coalesced load
    }
    __syncthreads();

    float2 v[16];
    #pragma unroll
    for (int s = 0; s < 16; ++s) v[s] = buf[wid][(lane + 32 * s) ^ (8 * wid)];

    reg_fft16<true>(v);
    twiddle16_nat<true>(v, lane, 0.012271846303085130f);
    #pragma unroll
    for (int r = 0; r < 16; ++r) S[wid][crev(r, 4)][lane] = v[r];
    __syncwarp();

    const int k1 = lane & 15, k2 = lane >> 4;
    {
        float2 w = make_float2(1.f, 0.f), wq;
        __sincosf(0.19634954084936207f * (float)k2, &wq.y, &wq.x);  // conj W32^{k2}
        const float sgn = k2 ? -1.f : 1.f;
        #pragma unroll
        for (int a = 0; a < 16; ++a) {
            float2 L0 = S[wid][k1][a];
            float2 L1 = S[wid][k1][a + 16];
            float2 hh = make_float2(L0.x + sgn * L1.x, L0.y + sgn * L1.y);
            v[a] = cmul(hh, w);
            w = cmul(w, wq);
        }
    }
    reg_fft16<true>(v);                   // v[r] = y_row[lane + 32*crev(r)]

    if (h < HH) {
        const float scale = 2.1073424255447017e-8f;   // 131072^-1.5 = 2^-25.5
        float* py = y + (size_t)(c * HH + h) * WW;
        #pragma unroll
        for (int r = 0; r < 16; ++r) {
            int m = lane + 32 * crev(r, 4);
            if (m < WW) py[m] = v[r].x * scale;       // 128B coalesced per instr
        }
    }
}

extern "C" void kernel_launch(void* const* d_in, const int* in_sizes, int n_in,
                              void* d_out, int out_size) {
    const float* u = (const float*)d_in[0];
    const float* k = (const float*)d_in[1];
    float* y = (float*)d_out;

    fftconv_k1<<<dim3(64, CH), 128>>>(u, k);     // all 256 padded rows
    fftconv_k2<<<dim3(33, CH), 256>>>();         // 257 column pairs, 8/block
    fftconv_k3<<<dim3(63, CH), 128>>>(y);        // rows 0..250
}

// round 4
// speedup vs baseline: 3.0516x; 1.2332x over previous
#include <cuda_runtime.h>
#include <cuda_fp16.h>

#define CH 256     // B*C channels
#define HH 251
#define WW 509
#define HP 256
#define WP 512

// scratch: per channel a WPxHP fp16-complex grid, w-major: A[c][w][h]
__device__ __align__(16) __half2 g_A[(size_t)CH * WP * HP];   // 128 MB

__device__ __forceinline__ float2 cmul(float2 a, float2 b) {
    return make_float2(fmaf(a.x, b.x, -a.y * b.y),
                       fmaf(a.x, b.y,  a.y * b.x));
}

// bit-reverse of a compile-time-constant index (folds under #pragma unroll)
__device__ __forceinline__ int crev(int x, int bits) {
    int r = 0;
    #pragma unroll
    for (int i = 0; i < 5; ++i)
        if (i < bits) r |= ((x >> i) & 1) << (bits - 1 - i);
    return r;
}

// 16-point DIF FFT in registers. Input natural order; output v[r] = X[crev(r,4)].
template<bool INV>
__device__ __forceinline__ void reg_fft16(float2* v) {
    const float C[8] = { 1.f,  0.9238795325112867f,  0.7071067811865476f,  0.3826834323650898f,
                         0.f, -0.3826834323650898f, -0.7071067811865476f, -0.9238795325112867f};
    const float S[8] = { 0.f, -0.3826834323650898f, -0.7071067811865476f, -0.9238795325112867f,
                        -1.f, -0.9238795325112867f, -0.7071067811865476f, -0.3826834323650898f};
    #pragma unroll
    for (int m = 8; m >= 1; m >>= 1) {
        #pragma unroll
        for (int b = 0; b < 16; b += 2 * m) {
            #pragma unroll
            for (int i = 0; i < m; ++i) {
                float2 lo = v[b + i], hi = v[b + i + m];
                v[b + i] = make_float2(lo.x + hi.x, lo.y + hi.y);
                float2 d = make_float2(lo.x - hi.x, lo.y - hi.y);
                const int j = i * (8 / m);
                if (j == 0) {
                    v[b + i + m] = d;
                } else {
                    float2 wt = make_float2(C[j], INV ? -S[j] : S[j]);
                    v[b + i + m] = cmul(d, wt);
                }
            }
        }
    }
}

// twiddle: v[slot holding k1=c] *= W_N^{+/- t*c}, iterated in natural c order.
template<bool INV>
__device__ __forceinline__ void twiddle16_nat(float2* v, int t, float twoPiOverN) {
    float ang = (INV ? twoPiOverN : -twoPiOverN) * (float)t;
    float2 wb; __sincosf(ang, &wb.y, &wb.x);
    float2 w = wb;
    #pragma unroll
    for (int c = 1; c < 16; ++c) {
        v[crev(c, 4)] = cmul(v[crev(c, 4)], w);
        w = cmul(w, wb);
    }
}

// K1: rows. z = u + i*k (zero padded), FFT-512 (16reg x [16reg x 2-fold]),
// fp16 transposed store. One warp/row, 4 rows/block. half2 staging aliases S.
__global__ void __launch_bounds__(128) fftconv_k1(const float* __restrict__ u,
                                                  const float* __restrict__ kk) {
    __shared__ __align__(16) float2 S[4][16][33];   // 16.9 KB; tail doubles as staging
    const int tid = threadIdx.x;
    const int lane = tid & 31, wid = tid >> 5;
    const int c = blockIdx.y;
    const int h = blockIdx.x * 4 + wid;

    float2 v[16];
    if (h < HH) {
        const float* pu = u + (size_t)(c * HH + h) * WW;
        const float* pk = kk + (size_t)(c * HH + h) * WW;
        #pragma unroll
        for (int s = 0; s < 16; ++s) {
            int n = lane + 32 * s;
            bool ok = n < WW;
            v[s].x = ok ? pu[n] : 0.f;
            v[s].y = ok ? pk[n] : 0.f;
        }
    } else {
        #pragma unroll
        for (int s = 0; s < 16; ++s) v[s] = make_float2(0.f, 0.f);
    }

    reg_fft16<false>(v);
    twiddle16_nat<false>(v, lane, 0.012271846303085130f);   // W512^{t*k1}
    #pragma unroll
    for (int r = 0; r < 16; ++r) S[wid][crev(r, 4)][lane] = v[r];
    __syncwarp();

    // FFT-32 over t: fold t=a+16b (smem broadcast), then reg FFT-16 over a
    const int k1 = lane & 15, k2 = lane >> 4;
    {
        float2 w = make_float2(1.f, 0.f), wq;
        __sincosf(-0.19634954084936207f * (float)k2, &wq.y, &wq.x);
        const float sgn = k2 ? -1.f : 1.f;
        #pragma unroll
        for (int a = 0; a < 16; ++a) {
            float2 L0 = S[wid][k1][a];
            float2 L1 = S[wid][k1][a + 16];
            float2 hh = make_float2(L0.x + sgn * L1.x, L0.y + sgn * L1.y);
            v[a] = cmul(hh, w);
            w = cmul(w, wq);
        }
    }
    reg_fft16<false>(v);                  // v[r] = X[lane + 32*crev(r)]
    __syncwarp();                         // S reads done; alias as half2 row

    __half2* brow = (__half2*)&S[wid][0][0];     // 512 half2 fits in 4224B row
    #pragma unroll
    for (int r = 0; r < 16; ++r) {
        int k = lane + 32 * crev(r, 4);
        brow[k] = __floats2half2_rn(v[r].x, v[r].y);
    }
    __syncthreads();

    __half2* out = g_A + (size_t)c * (WP * HP) + blockIdx.x * 4;
    #pragma unroll
    for (int q = 0; q < 4; ++q) {
        int w = tid + 128 * q;
        __half2 a0 = ((const __half2*)&S[0][0][0])[w];
        __half2 a1 = ((const __half2*)&S[1][0][0])[w];
        __half2 a2 = ((const __half2*)&S[2][0][0])[w];
        __half2 a3 = ((const __half2*)&S[3][0][0])[w];
        uint4 t;
        t.x = *reinterpret_cast<unsigned*>(&a0);
        t.y = *reinterpret_cast<unsigned*>(&a1);
        t.z = *reinterpret_cast<unsigned*>(&a2);
        t.w = *reinterpret_cast<unsigned*>(&a3);
        *reinterpret_cast<uint4*>(out + (size_t)w * HP) = t;   // 16B per w
    }
}

// K2: column pair (w, 512-w): FFT-256 (16x16), Hermitian split, P=U*K * 2^-12,
// IFFT-256, fp16. One warp per pair; coalesced 16B loads/stores via staging.
__global__ void __launch_bounds__(256) fftconv_k2() {
    __shared__ __align__(16) float2 R[8][2][272];   // per warp/half: transpose+Z (+staging alias)
    const int tid = threadIdx.x;
    const int lane = tid & 31, wp = tid >> 5;
    const int half = lane >> 4, tl = lane & 15;
    const int p = blockIdx.x * 8 + wp;
    if (p > 256) return;                  // no __syncthreads in this kernel
    const int w = p, w2 = (WP - w) & (WP - 1);
    const int c = blockIdx.y;
    __half2* gcol  = g_A + (size_t)c * (WP * HP) + (size_t)w  * HP;
    __half2* gcol2 = g_A + (size_t)c * (WP * HP) + (size_t)w2 * HP;
    float2* T    = &R[wp][half][0];       // own region (transpose / Zown / staging)
    float2* Zoth = &R[wp][half ^ 1][0];
    __half2* h0v = (__half2*)&R[wp][0][0];
    __half2* h1v = (__half2*)&R[wp][1][0];

    // warp-cooperative coalesced load of both columns (1KB each) into staging
    {
        const uint4* a4 = (const uint4*)gcol;
        const uint4* b4 = (const uint4*)gcol2;
        uint4 ta0 = a4[lane], ta1 = a4[lane + 32];
        uint4 tb0 = b4[lane], tb1 = b4[lane + 32];
        ((uint4*)h0v)[lane] = ta0; ((uint4*)h0v)[lane + 32] = ta1;
        ((uint4*)h1v)[lane] = tb0; ((uint4*)h1v)[lane + 32] = tb1;
    }
    __syncwarp();
    __half2* own = half ? h1v : h0v;
    float2 v[16];
    #pragma unroll
    for (int s = 0; s < 16; ++s) v[s] = __half22float2(own[tl + 16 * s]);
    __syncwarp();                         // staging reads done before T overwrite

    reg_fft16<false>(v);
    twiddle16_nat<false>(v, tl, 0.024543692606170260f);
    #pragma unroll
    for (int r = 0; r < 16; ++r) T[crev(r, 4) * 17 + tl] = v[r];
    __syncwarp();
    #pragma unroll
    for (int j = 0; j < 16; ++j) v[j] = T[tl * 17 + j];
    reg_fft16<false>(v);                  // v[r] = Z[tl + 16*crev(r)] of own col
    __syncwarp();                         // transpose reads done before Z overwrite

    #pragma unroll
    for (int r = 0; r < 16; ++r) T[tl + 16 * crev(r, 4)] = v[r];   // Zown natural-k
    __syncwarp();
    #pragma unroll
    for (int r = 0; r < 16; ++r) {
        int k = tl + 16 * crev(r, 4);
        int km = (HP - k) & (HP - 1);
        float2 z1 = v[r];                 // Z(k, w_self)
        float2 z2 = Zoth[km];             // Z(-k, -w_self)
        float2 uf = make_float2(0.5f * (z1.x + z2.x),  0.5f * (z1.y - z2.y));
        float2 kf = make_float2(0.5f * (z1.y + z2.y), -0.5f * (z1.x - z2.x));
        v[r] = cmul(uf, kf);
    }
    __syncwarp();                         // Hermitian cross-reads done

    // inverse: relabel bit-reversed hold -> natural, then 16x16 inverse
    float2 v2[16];
    #pragma unroll
    for (int r = 0; r < 16; ++r) v2[crev(r, 4)] = v[r];
    reg_fft16<true>(v2);
    twiddle16_nat<true>(v2, tl, 0.024543692606170260f);
    #pragma unroll
    for (int r = 0; r < 16; ++r) T[crev(r, 4) * 17 + tl] = v2[r];
    __syncwarp();
    #pragma unroll
    for (int j = 0; j < 16; ++j) v2[j] = T[tl * 17 + j];
    reg_fft16<true>(v2);                  // y[tl + 16*crev(r)]
    __syncwarp();                         // T reads done before half2 staging

    const float SC2 = 0.000244140625f;    // 2^-12 prescale (fp16 range)
    #pragma unroll
    for (int r = 0; r < 16; ++r)
        own[tl + 16 * crev(r, 4)] = __floats2half2_rn(v2[r].x * SC2, v2[r].y * SC2);
    __syncwarp();

    {   // warp-cooperative coalesced store
        uint4* a4 = (uint4*)gcol;
        a4[lane] = ((uint4*)h0v)[lane]; a4[lane + 32] = ((uint4*)h0v)[lane + 32];
        if (w2 != w) {
            uint4* b4 = (uint4*)gcol2;
            b4[lane] = ((uint4*)h1v)[lane]; b4[lane + 32] = ((uint4*)h1v)[lane + 32];
        }
    }
}

// K3: rows. IFFT-512, real part * 2^-13.5, cropped coalesced store.
__global__ void __launch_bounds__(128) fftconv_k3(float* __restrict__ y) {
    __shared__ __align__(16) float2 S[4][16][33];
    const int tid = threadIdx.x;
    const int lane = tid & 31, wid = tid >> 5;
    const int c = blockIdx.y;
    const int h0 = blockIdx.x * 4;
    const int h = h0 + wid;

    const __half2* in = g_A + (size_t)c * (WP * HP) + h0;
    #pragma unroll
    for (int q = 0; q < 4; ++q) {
        int w = tid + 128 * q;
        uint4 t = *reinterpret_cast<const uint4*>(in + (size_t)w * HP);
        ((__half2*)&S[0][0][0])[w] = *reinterpret_cast<__half2*>(&t.x);
        ((__half2*)&S[1][0][0])[w] = *reinterpret_cast<__half2*>(&t.y);
        ((__half2*)&S[2][0][0])[w] = *reinterpret_cast<__half2*>(&t.z);
        ((__half2*)&S[3][0][0])[w] = *reinterpret_cast<__half2*>(&t.w);
    }
    __syncthreads();

    float2 v[16];
    const __half2* brow = (const __half2*)&S[wid][0][0];
    #pragma unroll
    for (int s = 0; s < 16; ++s) v[s] = __half22float2(brow[lane + 32 * s]);
    __syncwarp();                         // staging reads done before S overwrite

    reg_fft16<true>(v);
    twiddle16_nat<true>(v, lane, 0.012271846303085130f);
    #pragma unroll
    for (int r = 0; r < 16; ++r) S[wid][crev(r, 4)][lane] = v[r];
    __syncwarp();

    const int k1 = lane & 15, k2 = lane >> 4;
    {
        float2 w = make_float2(1.f, 0.f), wq;
        __sincosf(0.19634954084936207f * (float)k2, &wq.y, &wq.x);   // conj
        const float sgn = k2 ? -1.f : 1.f;
        #pragma unroll
        for (int a = 0; a < 16; ++a) {
            float2 L0 = S[wid][k1][a];
            float2 L1 = S[wid][k1][a + 16];
            float2 hh = make_float2(L0.x + sgn * L1.x, L0.y + sgn * L1.y);
            v[a] = cmul(hh, w);
            w = cmul(w, wq);
        }
    }
    reg_fft16<true>(v);                   // v[r] = y_row[lane + 32*crev(r)]

    if (h < HH) {
        const float scale = 8.6316745750903e-05f;   // 2^-13.5 (rest of 2^-25.5)
        float* py = y + (size_t)(c * HH + h) * WW;
        #pragma unroll
        for (int r = 0; r < 16; ++r) {
            int m = lane + 32 * crev(r, 4);
            if (m < WW) py[m] = v[r].x * scale;
        }
    }
}

extern "C" void kernel_launch(void* const* d_in, const int* in_sizes, int n_in,
                              void* d_out, int out_size) {
    const float* u = (const float*)d_in[0];
    const float* k = (const float*)d_in[1];
    float* y = (float*)d_out;

    fftconv_k1<<<dim3(64, CH), 128>>>(u, k);     // all 256 padded rows
    fftconv_k2<<<dim3(33, CH), 256>>>();         // 257 column pairs, 8/block
    fftconv_k3<<<dim3(63, CH), 128>>>(y);        // rows 0..250
}

// round 5
// speedup vs baseline: 3.3290x; 1.0909x over previous
#include <cuda_runtime.h>
#include <cuda_fp16.h>

#define CH 256     // B*C channels
#define HH 251
#define WW 509
#define HP 256
#define WP 512

// scratch: per channel a WPxHP fp16-complex grid, w-major: A[c][w][h]
__device__ __align__(16) __half2 g_A[(size_t)CH * WP * HP];   // 128 MB

__device__ __forceinline__ float2 cmul(float2 a, float2 b) {
    return make_float2(fmaf(a.x, b.x, -a.y * b.y),
                       fmaf(a.x, b.y,  a.y * b.x));
}

// bit-reverse of a compile-time-constant index (folds under #pragma unroll)
__device__ __forceinline__ int crev(int x, int bits) {
    int r = 0;
    #pragma unroll
    for (int i = 0; i < 5; ++i)
        if (i < bits) r |= ((x >> i) & 1) << (bits - 1 - i);
    return r;
}

// 16-point DIF FFT in registers. Input natural order; output v[r] = X[crev(r,4)].
template<bool INV>
__device__ __forceinline__ void reg_fft16(float2* v) {
    const float C[8] = { 1.f,  0.9238795325112867f,  0.7071067811865476f,  0.3826834323650898f,
                         0.f, -0.3826834323650898f, -0.7071067811865476f, -0.9238795325112867f};
    const float S[8] = { 0.f, -0.3826834323650898f, -0.7071067811865476f, -0.9238795325112867f,
                        -1.f, -0.9238795325112867f, -0.7071067811865476f, -0.3826834323650898f};
    #pragma unroll
    for (int m = 8; m >= 1; m >>= 1) {
        #pragma unroll
        for (int b = 0; b < 16; b += 2 * m) {
            #pragma unroll
            for (int i = 0; i < m; ++i) {
                float2 lo = v[b + i], hi = v[b + i + m];
                v[b + i] = make_float2(lo.x + hi.x, lo.y + hi.y);
                float2 d = make_float2(lo.x - hi.x, lo.y - hi.y);
                const int j = i * (8 / m);
                if (j == 0) {
                    v[b + i + m] = d;
                } else {
                    float2 wt = make_float2(C[j], INV ? -S[j] : S[j]);
                    v[b + i + m] = cmul(d, wt);
                }
            }
        }
    }
}

// twiddle: v[slot holding k1=c] *= W_N^{+/- t*c}, iterated in natural c order.
template<bool INV>
__device__ __forceinline__ void twiddle16_nat(float2* v, int t, float twoPiOverN) {
    float ang = (INV ? twoPiOverN : -twoPiOverN) * (float)t;
    float2 wb; __sincosf(ang, &wb.y, &wb.x);
    float2 w = wb;
    #pragma unroll
    for (int c = 1; c < 16; ++c) {
        v[crev(c, 4)] = cmul(v[crev(c, 4)], w);
        w = cmul(w, wb);
    }
}

// K1: rows. z = u + i*k (zero padded), FFT-512 (16reg x [16reg x 2-fold]),
// fp16 transposed store, h-tile=8 (full 32B sectors). 8 warps = 8 rows/block.
__global__ void __launch_bounds__(256) fftconv_k1(const float* __restrict__ u,
                                                  const float* __restrict__ kk) {
    __shared__ __align__(16) float2 S[8][16][33];   // 33.8 KB; rows alias half2 staging
    const int tid = threadIdx.x;
    const int lane = tid & 31, wid = tid >> 5;
    const int c = blockIdx.y;
    const int h = blockIdx.x * 8 + wid;

    float2 v[16];
    if (h < HH) {
        const float* pu = u + (size_t)(c * HH + h) * WW;
        const float* pk = kk + (size_t)(c * HH + h) * WW;
        #pragma unroll
        for (int s = 0; s < 16; ++s) {
            int n = lane + 32 * s;
            bool ok = n < WW;
            v[s].x = ok ? pu[n] : 0.f;
            v[s].y = ok ? pk[n] : 0.f;
        }
    } else {
        #pragma unroll
        for (int s = 0; s < 16; ++s) v[s] = make_float2(0.f, 0.f);
    }

    reg_fft16<false>(v);
    twiddle16_nat<false>(v, lane, 0.012271846303085130f);   // W512^{t*k1}
    #pragma unroll
    for (int r = 0; r < 16; ++r) S[wid][crev(r, 4)][lane] = v[r];
    __syncwarp();

    // FFT-32 over t: fold t=a+16b (smem broadcast), then reg FFT-16 over a
    const int k1 = lane & 15, k2 = lane >> 4;
    {
        float2 w = make_float2(1.f, 0.f), wq;
        __sincosf(-0.19634954084936207f * (float)k2, &wq.y, &wq.x);
        const float sgn = k2 ? -1.f : 1.f;
        #pragma unroll
        for (int a = 0; a < 16; ++a) {
            float2 L0 = S[wid][k1][a];
            float2 L1 = S[wid][k1][a + 16];
            float2 hh = make_float2(L0.x + sgn * L1.x, L0.y + sgn * L1.y);
            v[a] = cmul(hh, w);
            w = cmul(w, wq);
        }
    }
    reg_fft16<false>(v);                  // v[r] = X[lane + 32*crev(r)]
    __syncwarp();                         // S reads done; alias row as half2

    __half2* brow = (__half2*)&S[wid][0][0];     // 512 half2 = 2048B < 4224B row
    #pragma unroll
    for (int r = 0; r < 16; ++r) {
        int k = lane + 32 * crev(r, 4);
        brow[k] = __floats2half2_rn(v[r].x, v[r].y);
    }
    __syncthreads();

    __half2* out = g_A + (size_t)c * (WP * HP) + blockIdx.x * 8;
    #pragma unroll
    for (int q = 0; q < 2; ++q) {
        int w = tid + 256 * q;
        __half2 a0 = ((const __half2*)&S[0][0][0])[w];
        __half2 a1 = ((const __half2*)&S[1][0][0])[w];
        __half2 a2 = ((const __half2*)&S[2][0][0])[w];
        __half2 a3 = ((const __half2*)&S[3][0][0])[w];
        __half2 a4 = ((const __half2*)&S[4][0][0])[w];
        __half2 a5 = ((const __half2*)&S[5][0][0])[w];
        __half2 a6 = ((const __half2*)&S[6][0][0])[w];
        __half2 a7 = ((const __half2*)&S[7][0][0])[w];
        uint4 t0, t1;
        t0.x = *reinterpret_cast<unsigned*>(&a0);
        t0.y = *reinterpret_cast<unsigned*>(&a1);
        t0.z = *reinterpret_cast<unsigned*>(&a2);
        t0.w = *reinterpret_cast<unsigned*>(&a3);
        t1.x = *reinterpret_cast<unsigned*>(&a4);
        t1.y = *reinterpret_cast<unsigned*>(&a5);
        t1.z = *reinterpret_cast<unsigned*>(&a6);
        t1.w = *reinterpret_cast<unsigned*>(&a7);
        uint4* dst = reinterpret_cast<uint4*>(out + (size_t)w * HP);
        dst[0] = t0;                      // 32B: full sector per (w, h-tile)
        dst[1] = t1;
    }
}

// K2: column pair (w, 512-w): FFT-256 (16x16), Hermitian split, P=U*K * 2^-12,
// IFFT-256 for the w<=256 column ONLY (G(h,512-w)=conj(G(h,w)) is implicit).
// One warp per pair; channel order reversed for L2 temporal locality.
__global__ void __launch_bounds__(256) fftconv_k2() {
    __shared__ __align__(16) float2 R[8][2][272];   // per warp/half: staging+T+Z alias
    const int tid = threadIdx.x;
    const int lane = tid & 31, wp = tid >> 5;
    const int half = lane >> 4, tl = lane & 15;
    const int p = blockIdx.x * 8 + wp;
    if (p > 256) return;                  // no __syncthreads in this kernel
    const int w = p, w2 = (WP - w) & (WP - 1);
    const int c = 255 - blockIdx.y;       // reversed: read K1's youngest L2 lines
    __half2* gcol  = g_A + (size_t)c * (WP * HP) + (size_t)w  * HP;
    __half2* gcol2 = g_A + (size_t)c * (WP * HP) + (size_t)w2 * HP;
    float2* T    = &R[wp][half][0];       // own region (staging / transpose / Z)
    float2* Zoth = &R[wp][half ^ 1][0];
    __half2* h0v = (__half2*)&R[wp][0][0];
    __half2* h1v = (__half2*)&R[wp][1][0];

    // warp-cooperative coalesced load of both columns (1KB each) into staging
    {
        const uint4* a4 = (const uint4*)gcol;
        const uint4* b4 = (const uint4*)gcol2;
        uint4 ta0 = a4[lane], ta1 = a4[lane + 32];
        uint4 tb0 = b4[lane], tb1 = b4[lane + 32];
        ((uint4*)h0v)[lane] = ta0; ((uint4*)h0v)[lane + 32] = ta1;
        ((uint4*)h1v)[lane] = tb0; ((uint4*)h1v)[lane + 32] = tb1;
    }
    __syncwarp();
    __half2* own = half ? h1v : h0v;
    float2 v[16];
    #pragma unroll
    for (int s = 0; s < 16; ++s) v[s] = __half22float2(own[tl + 16 * s]);
    __syncwarp();                         // staging reads done before T overwrite

    reg_fft16<false>(v);
    twiddle16_nat<false>(v, tl, 0.024543692606170260f);
    #pragma unroll
    for (int r = 0; r < 16; ++r) T[crev(r, 4) * 17 + tl] = v[r];
    __syncwarp();
    #pragma unroll
    for (int j = 0; j < 16; ++j) v[j] = T[tl * 17 + j];
    reg_fft16<false>(v);                  // v[r] = Z[tl + 16*crev(r)] of own col
    __syncwarp();                         // transpose reads done before Z overwrite

    #pragma unroll
    for (int r = 0; r < 16; ++r) T[tl + 16 * crev(r, 4)] = v[r];   // Zown natural-k
    __syncwarp();

    float2 v2[16];
    if (half == 0) {                      // only the stored column needs P
        #pragma unroll
        for (int r = 0; r < 16; ++r) {
            int k = tl + 16 * crev(r, 4);
            int km = (HP - k) & (HP - 1);
            float2 z1 = v[r];             // Z(k, w)
            float2 z2 = Zoth[km];         // Z(-k, -w)
            float2 uf = make_float2(0.5f * (z1.x + z2.x),  0.5f * (z1.y - z2.y));
            float2 kf = make_float2(0.5f * (z1.y + z2.y), -0.5f * (z1.x - z2.x));
            float2 pp = cmul(uf, kf);
            v2[crev(r, 4)] = pp;          // relabel bit-reversed -> natural
        }
    }
    __syncwarp();                         // Zoth reads done

    if (half == 0) {
        reg_fft16<true>(v2);
        twiddle16_nat<true>(v2, tl, 0.024543692606170260f);
        #pragma unroll
        for (int r = 0; r < 16; ++r) T[crev(r, 4) * 17 + tl] = v2[r];
    }
    __syncwarp();
    if (half == 0) {
        #pragma unroll
        for (int j = 0; j < 16; ++j) v2[j] = T[tl * 17 + j];
        reg_fft16<true>(v2);              // G[tl + 16*crev(r)]
    }
    __syncwarp();                         // T reads done before half2 staging
    if (half == 0) {
        const float SC2 = 0.000244140625f;    // 2^-12 prescale (fp16 range)
        #pragma unroll
        for (int r = 0; r < 16; ++r)
            h0v[tl + 16 * crev(r, 4)] = __floats2half2_rn(v2[r].x * SC2, v2[r].y * SC2);
    }
    __syncwarp();

    {   // warp-cooperative coalesced store of column w only
        uint4* a4 = (uint4*)gcol;
        a4[lane] = ((uint4*)h0v)[lane];
        a4[lane + 32] = ((uint4*)h0v)[lane + 32];
    }
}

// K3: rows. Read G columns w=0..256, reconstruct w>256 by conjugation,
// IFFT-512, real part * 2^-13.5, cropped coalesced store. 8 rows/block.
__global__ void __launch_bounds__(256) fftconv_k3(float* __restrict__ y) {
    __shared__ __align__(16) float2 S[8][16][33];   // rows alias half2 staging
    const int tid = threadIdx.x;
    const int lane = tid & 31, wid = tid >> 5;
    const int c = blockIdx.y;             // ascending: reads K2's youngest writes
    const int h0 = blockIdx.x * 8;
    const int h = h0 + wid;

    const __half2* in = g_A + (size_t)c * (WP * HP) + h0;
    {   // staging fill: columns w = 0..255 (one per thread), 2x16B = full sector
        int w = tid;
        const uint4* src = (const uint4*)(in + (size_t)w * HP);
        uint4 t0 = src[0], t1 = src[1];
        ((__half2*)&S[0][0][0])[w] = *reinterpret_cast<__half2*>(&t0.x);
        ((__half2*)&S[1][0][0])[w] = *reinterpret_cast<__half2*>(&t0.y);
        ((__half2*)&S[2][0][0])[w] = *reinterpret_cast<__half2*>(&t0.z);
        ((__half2*)&S[3][0][0])[w] = *reinterpret_cast<__half2*>(&t0.w);
        ((__half2*)&S[4][0][0])[w] = *reinterpret_cast<__half2*>(&t1.x);
        ((__half2*)&S[5][0][0])[w] = *reinterpret_cast<__half2*>(&t1.y);
        ((__half2*)&S[6][0][0])[w] = *reinterpret_cast<__half2*>(&t1.z);
        ((__half2*)&S[7][0][0])[w] = *reinterpret_cast<__half2*>(&t1.w);
    }
    if (tid < 2) {                        // column w = 256
        const uint4* src = (const uint4*)(in + (size_t)256 * HP);
        uint4 t = src[tid];
        ((__half2*)&S[4 * tid + 0][0][0])[256] = *reinterpret_cast<__half2*>(&t.x);
        ((__half2*)&S[4 * tid + 1][0][0])[256] = *reinterpret_cast<__half2*>(&t.y);
        ((__half2*)&S[4 * tid + 2][0][0])[256] = *reinterpret_cast<__half2*>(&t.z);
        ((__half2*)&S[4 * tid + 3][0][0])[256] = *reinterpret_cast<__half2*>(&t.w);
    }
    __syncthreads();

    float2 v[16];
    const __half2* brow = (const __half2*)&S[wid][0][0];
    #pragma unroll
    for (int s = 0; s < 16; ++s) {
        int m = lane + 32 * s;
        if (m <= 256) {
            v[s] = __half22float2(brow[m]);
        } else {
            v[s] = __half22float2(brow[512 - m]);
            v[s].y = -v[s].y;             // G(h, m) = conj(G(h, 512-m))
        }
    }
    __syncwarp();                         // staging reads done before S overwrite

    reg_fft16<true>(v);
    twiddle16_nat<true>(v, lane, 0.012271846303085130f);
    #pragma unroll
    for (int r = 0; r < 16; ++r) S[wid][crev(r, 4)][lane] = v[r];
    __syncwarp();

    const int k1 = lane & 15, k2 = lane >> 4;
    {
        float2 w = make_float2(1.f, 0.f), wq;
        __sincosf(0.19634954084936207f * (float)k2, &wq.y, &wq.x);   // conj
        const float sgn = k2 ? -1.f : 1.f;
        #pragma unroll
        for (int a = 0; a < 16; ++a) {
            float2 L0 = S[wid][k1][a];
            float2 L1 = S[wid][k1][a + 16];
            float2 hh = make_float2(L0.x + sgn * L1.x, L0.y + sgn * L1.y);
            v[a] = cmul(hh, w);
            w = cmul(w, wq);
        }
    }
    reg_fft16<true>(v);                   // v[r] = y_row[lane + 32*crev(r)]

    if (h < HH) {
        const float scale = 8.6316745750903e-05f;   // 2^-13.5 (rest of 2^-25.5)
        float* py = y + (size_t)(c * HH + h) * WW;
        #pragma unroll
        for (int r = 0; r < 16; ++r) {
            int m = lane + 32 * crev(r, 4);
            if (m < WW) py[m] = v[r].x * scale;
        }
    }
}

extern "C" void kernel_launch(void* const* d_in, const int* in_sizes, int n_in,
                              void* d_out, int out_size) {
    const float* u = (const float*)d_in[0];
    const float* k = (const float*)d_in[1];
    float* y = (float*)d_out;

    fftconv_k1<<<dim3(32, CH), 256>>>(u, k);     // all 256 padded rows, 8/block
    fftconv_k2<<<dim3(33, CH), 256>>>();         // 257 column pairs, 8/block
    fftconv_k3<<<dim3(32, CH), 256>>>(y);        // rows 0..250, 8/block
}

// round 6
// speedup vs baseline: 3.5122x; 1.0551x over previous
#include <cuda_runtime.h>
#include <cuda_fp16.h>

#define CH 256     // B*C channels
#define HH 251
#define WW 509
#define HP 256
#define WP 512

// scratch: per channel, layout [seg][w][hL], seg=h>>3 (32), w (512), hL=h&7 (8)
__device__ __align__(16) __half2 g_A[(size_t)CH * WP * HP];   // 128 MB

__device__ __forceinline__ float2 cmul(float2 a, float2 b) {
    return make_float2(fmaf(a.x, b.x, -a.y * b.y),
                       fmaf(a.x, b.y,  a.y * b.x));
}

// bit-reverse of a compile-time-constant index (folds under #pragma unroll)
__device__ __forceinline__ int crev(int x, int bits) {
    int r = 0;
    #pragma unroll
    for (int i = 0; i < 5; ++i)
        if (i < bits) r |= ((x >> i) & 1) << (bits - 1 - i);
    return r;
}

// 16-point DIF FFT in registers. Input natural order; output v[r] = X[crev(r,4)].
template<bool INV>
__device__ __forceinline__ void reg_fft16(float2* v) {
    const float C[8] = { 1.f,  0.9238795325112867f,  0.7071067811865476f,  0.3826834323650898f,
                         0.f, -0.3826834323650898f, -0.7071067811865476f, -0.9238795325112867f};
    const float S[8] = { 0.f, -0.3826834323650898f, -0.7071067811865476f, -0.9238795325112867f,
                        -1.f, -0.9238795325112867f, -0.7071067811865476f, -0.3826834323650898f};
    #pragma unroll
    for (int m = 8; m >= 1; m >>= 1) {
        #pragma unroll
        for (int b = 0; b < 16; b += 2 * m) {
            #pragma unroll
            for (int i = 0; i < m; ++i) {
                float2 lo = v[b + i], hi = v[b + i + m];
                v[b + i] = make_float2(lo.x + hi.x, lo.y + hi.y);
                float2 d = make_float2(lo.x - hi.x, lo.y - hi.y);
                const int j = i * (8 / m);
                if (j == 0) {
                    v[b + i + m] = d;
                } else {
                    float2 wt = make_float2(C[j], INV ? -S[j] : S[j]);
                    v[b + i + m] = cmul(d, wt);
                }
            }
        }
    }
}

// twiddle: v[slot holding k1=c] *= W_N^{+/- t*c}, iterated in natural c order.
template<bool INV>
__device__ __forceinline__ void twiddle16_nat(float2* v, int t, float twoPiOverN) {
    float ang = (INV ? twoPiOverN : -twoPiOverN) * (float)t;
    float2 wb; __sincosf(ang, &wb.y, &wb.x);
    float2 w = wb;
    #pragma unroll
    for (int c = 1; c < 16; ++c) {
        v[crev(c, 4)] = cmul(v[crev(c, 4)], w);
        w = cmul(w, wb);
    }
}

// K1: rows. z = u + i*k (zero padded), FFT-512 (16reg x [16reg x 2-fold]),
// fp16 store into [seg][w][hL] -> 16KB fully contiguous per block.
__global__ void __launch_bounds__(256) fftconv_k1(const float* __restrict__ u,
                                                  const float* __restrict__ kk) {
    __shared__ __align__(16) float2 S[8][16][33];   // 33.8 KB; rows alias half2 staging
    const int tid = threadIdx.x;
    const int lane = tid & 31, wid = tid >> 5;
    const int c = blockIdx.y;
    const int seg = blockIdx.x;
    const int h = seg * 8 + wid;

    float2 v[16];
    if (h < HH) {
        const float* pu = u + (size_t)(c * HH + h) * WW;
        const float* pk = kk + (size_t)(c * HH + h) * WW;
        #pragma unroll
        for (int s = 0; s < 16; ++s) {
            int n = lane + 32 * s;
            bool ok = n < WW;
            v[s].x = ok ? pu[n] : 0.f;
            v[s].y = ok ? pk[n] : 0.f;
        }
    } else {
        #pragma unroll
        for (int s = 0; s < 16; ++s) v[s] = make_float2(0.f, 0.f);
    }

    reg_fft16<false>(v);
    twiddle16_nat<false>(v, lane, 0.012271846303085130f);   // W512^{t*k1}
    #pragma unroll
    for (int r = 0; r < 16; ++r) S[wid][crev(r, 4)][lane] = v[r];
    __syncwarp();

    // FFT-32 over t: fold t=a+16b (smem broadcast), then reg FFT-16 over a
    const int k1 = lane & 15, k2 = lane >> 4;
    {
        float2 w = make_float2(1.f, 0.f), wq;
        __sincosf(-0.19634954084936207f * (float)k2, &wq.y, &wq.x);
        const float sgn = k2 ? -1.f : 1.f;
        #pragma unroll
        for (int a = 0; a < 16; ++a) {
            float2 L0 = S[wid][k1][a];
            float2 L1 = S[wid][k1][a + 16];
            float2 hh = make_float2(L0.x + sgn * L1.x, L0.y + sgn * L1.y);
            v[a] = cmul(hh, w);
            w = cmul(w, wq);
        }
    }
    reg_fft16<false>(v);                  // v[r] = X[lane + 32*crev(r)]
    __syncwarp();                         // S reads done; alias row as half2

    __half2* brow = (__half2*)&S[wid][0][0];     // 512 half2 = 2048B < 4224B row
    #pragma unroll
    for (int r = 0; r < 16; ++r) {
        int k = lane + 32 * crev(r, 4);
        brow[k] = __floats2half2_rn(v[r].x, v[r].y);
    }
    __syncthreads();

    // contiguous 16KB store: uint4 li covers (w = li>>1, hL = (li&1)*4 + j)
    uint4* dst4 = (uint4*)(g_A + ((size_t)c * 32 + seg) * (512 * 8));
    #pragma unroll
    for (int q = 0; q < 4; ++q) {
        int li = tid + 256 * q;
        int w = li >> 1, part = li & 1;
        __half2 a0 = ((const __half2*)&S[part * 4 + 0][0][0])[w];
        __half2 a1 = ((const __half2*)&S[part * 4 + 1][0][0])[w];
        __half2 a2 = ((const __half2*)&S[part * 4 + 2][0][0])[w];
        __half2 a3 = ((const __half2*)&S[part * 4 + 3][0][0])[w];
        uint4 t;
        t.x = *reinterpret_cast<unsigned*>(&a0);
        t.y = *reinterpret_cast<unsigned*>(&a1);
        t.z = *reinterpret_cast<unsigned*>(&a2);
        t.w = *reinterpret_cast<unsigned*>(&a3);
        dst4[li] = t;                     // consecutive tid -> consecutive 16B
    }
}

// K2: column pair (w, 512-w): FFT-256 (16x16), Hermitian split, P=U*K * 2^-12,
// IFFT-256 + store for w<=256 only. Block-cooperative staging for coalescing.
__global__ void __launch_bounds__(256) fftconv_k2() {
    __shared__ __align__(16) char SM[34816];    // stage_in / R / stage_out time-shared
    __half2* stage_in  = (__half2*)SM;          // [(side*8+wi)*264 + h], 16.9 KB
    float2*  Rbase     = (float2*)SM;           // [(wp*2+half)*272], 34.8 KB
    __half2* stage_out = (__half2*)SM;          // [wi*264 + k], 8.4 KB
    const int tid = threadIdx.x;
    const int lane = tid & 31, wp = tid >> 5;
    const int half = lane >> 4, tl = lane & 15;
    const int c = 255 - blockIdx.y;       // reversed: read K1's youngest L2 lines
    const int w0 = blockIdx.x * 8;
    const int nc = (blockIdx.x == 32) ? 1 : 8;   // valid columns in this block
    const int p = w0 + wp;
    const bool valid = (wp < nc);
    const __half2* gch = g_A + (size_t)c * (32 * 512 * 8);

    // cooperative coalesced load: own columns (side 0) + mirrors (side 1)
    #pragma unroll
    for (int side = 0; side < 2; ++side) {
        for (int g = tid; g < nc * 32; g += 256) {
            int seg, wi;
            if (nc == 8) { seg = g >> 3; wi = g & 7; } else { seg = g; wi = 0; }
            int col = w0 + wi;
            if (side) col = (512 - col) & 511;
            const uint4* src4 = (const uint4*)(gch + ((size_t)seg * 512 + col) * 8);
            uint4 t0 = src4[0], t1 = src4[1];
            uint4* d4 = (uint4*)(stage_in + ((side * 8 + wi) * 264 + seg * 8));
            d4[0] = t0; d4[1] = t1;
        }
    }
    __syncthreads();

    float2 v[16];
    if (valid) {
        const __half2* own = stage_in + (half * 8 + wp) * 264;
        #pragma unroll
        for (int s = 0; s < 16; ++s) v[s] = __half22float2(own[tl + 16 * s]);
    }
    __syncthreads();                      // stage_in dead; R region live

    float2* T    = Rbase + (wp * 2 + half) * 272;
    float2* Zoth = Rbase + (wp * 2 + (half ^ 1)) * 272;
    float2 v2[16];
    if (valid) {
        reg_fft16<false>(v);
        twiddle16_nat<false>(v, tl, 0.024543692606170260f);
        #pragma unroll
        for (int r = 0; r < 16; ++r) T[crev(r, 4) * 17 + tl] = v[r];
        __syncwarp();
        #pragma unroll
        for (int j = 0; j < 16; ++j) v[j] = T[tl * 17 + j];
        reg_fft16<false>(v);              // v[r] = Z[tl + 16*crev(r)] of own col
        __syncwarp();                     // transpose reads done before Z overwrite

        #pragma unroll
        for (int r = 0; r < 16; ++r) T[tl + 16 * crev(r, 4)] = v[r];   // Z natural-k
        __syncwarp();

        if (half == 0) {                  // only the stored column needs P
            #pragma unroll
            for (int r = 0; r < 16; ++r) {
                int k = tl + 16 * crev(r, 4);
                int km = (HP - k) & (HP - 1);
                float2 z1 = v[r];         // Z(k, w)
                float2 z2 = Zoth[km];     // Z(-k, -w)
                float2 uf = make_float2(0.5f * (z1.x + z2.x),  0.5f * (z1.y - z2.y));
                float2 kf = make_float2(0.5f * (z1.y + z2.y), -0.5f * (z1.x - z2.x));
                v2[crev(r, 4)] = cmul(uf, kf);   // relabel bitrev -> natural
            }
        }
        __syncwarp();                     // Zoth reads done

        if (half == 0) {
            reg_fft16<true>(v2);
            twiddle16_nat<true>(v2, tl, 0.024543692606170260f);
            #pragma unroll
            for (int r = 0; r < 16; ++r) T[crev(r, 4) * 17 + tl] = v2[r];
        }
        __syncwarp();
        if (half == 0) {
            #pragma unroll
            for (int j = 0; j < 16; ++j) v2[j] = T[tl * 17 + j];
            reg_fft16<true>(v2);          // G[tl + 16*crev(r)]
        }
    }
    __syncthreads();                      // all T reads done; stage_out live

    if (valid && half == 0) {
        const float SC2 = 0.000244140625f;    // 2^-12 prescale (fp16 range)
        #pragma unroll
        for (int r = 0; r < 16; ++r)
            stage_out[wp * 264 + tl + 16 * crev(r, 4)] =
                __floats2half2_rn(v2[r].x * SC2, v2[r].y * SC2);
    }
    __syncthreads();

    // cooperative coalesced store of columns w0..w0+nc-1
    for (int g = tid; g < nc * 32; g += 256) {
        int seg, wi;
        if (nc == 8) { seg = g >> 3; wi = g & 7; } else { seg = g; wi = 0; }
        const uint4* s4 = (const uint4*)(stage_out + (wi * 264 + seg * 8));
        uint4 t0 = s4[0], t1 = s4[1];
        uint4* dst4 = (uint4*)((__half2*)gch + ((size_t)seg * 512 + w0 + wi) * 8);
        dst4[0] = t0; dst4[1] = t1;
    }
}

// K3: rows. Read seg slice w=0..256 (contiguous), reconstruct w>256 by conj,
// IFFT-512, real part * 2^-13.5, cropped coalesced store. 8 rows/block.
__global__ void __launch_bounds__(256) fftconv_k3(float* __restrict__ y) {
    __shared__ __align__(16) float2 S[8][16][33];   // rows alias half2 staging
    const int tid = threadIdx.x;
    const int lane = tid & 31, wid = tid >> 5;
    const int c = blockIdx.y;             // ascending: reads K2's youngest writes
    const int seg = blockIdx.x;
    const int h = seg * 8 + wid;

    // contiguous load: uint4 li covers (w = li>>1, hL = (li&1)*4 + j), w<=256
    const uint4* src4 = (const uint4*)(g_A + ((size_t)c * 32 + seg) * (512 * 8));
    for (int li = tid; li < 514; li += 256) {
        int w = li >> 1, part = li & 1;
        uint4 t = src4[li];
        ((__half2*)&S[part * 4 + 0][0][0])[w] = *reinterpret_cast<__half2*>(&t.x);
        ((__half2*)&S[part * 4 + 1][0][0])[w] = *reinterpret_cast<__half2*>(&t.y);
        ((__half2*)&S[part * 4 + 2][0][0])[w] = *reinterpret_cast<__half2*>(&t.z);
        ((__half2*)&S[part * 4 + 3][0][0])[w] = *reinterpret_cast<__half2*>(&t.w);
    }
    __syncthreads();

    float2 v[16];
    const __half2* brow = (const __half2*)&S[wid][0][0];
    #pragma unroll
    for (int s = 0; s < 16; ++s) {
        int m = lane + 32 * s;
        if (m <= 256) {
            v[s] = __half22float2(brow[m]);
        } else {
            v[s] = __half22float2(brow[512 - m]);
            v[s].y = -v[s].y;             // G(h, m) = conj(G(h, 512-m))
        }
    }
    __syncwarp();                         // staging reads done before S overwrite

    reg_fft16<true>(v);
    twiddle16_nat<true>(v, lane, 0.012271846303085130f);
    #pragma unroll
    for (int r = 0; r < 16; ++r) S[wid][crev(r, 4)][lane] = v[r];
    __syncwarp();

    const int k1 = lane & 15, k2 = lane >> 4;
    {
        float2 w = make_float2(1.f, 0.f), wq;
        __sincosf(0.19634954084936207f * (float)k2, &wq.y, &wq.x);   // conj
        const float sgn = k2 ? -1.f : 1.f;
        #pragma unroll
        for (int a = 0; a < 16; ++a) {
            float2 L0 = S[wid][k1][a];
            float2 L1 = S[wid][k1][a + 16];
            float2 hh = make_float2(L0.x + sgn * L1.x, L0.y + sgn * L1.y);
            v[a] = cmul(hh, w);
            w = cmul(w, wq);
        }
    }
    reg_fft16<true>(v);                   // v[r] = y_row[lane + 32*crev(r)]

    if (h < HH) {
        const float scale = 8.6316745750903e-05f;   // 2^-13.5 (rest of 2^-25.5)
        float* py = y + (size_t)(c * HH + h) * WW;
        #pragma unroll
        for (int r = 0; r < 16; ++r) {
            int m = lane + 32 * crev(r, 4);
            if (m < WW) py[m] = v[r].x * scale;
        }
    }
}

extern "C" void kernel_launch(void* const* d_in, const int* in_sizes, int n_in,
                              void* d_out, int out_size) {
    const float* u = (const float*)d_in[0];
    const float* k = (const float*)d_in[1];
    float* y = (float*)d_out;

    fftconv_k1<<<dim3(32, CH), 256>>>(u, k);     // seg 0..31 per channel
    fftconv_k2<<<dim3(33, CH), 256>>>();         // 257 column pairs, 8/block
    fftconv_k3<<<dim3(32, CH), 256>>>(y);        // seg 0..31, store h<251
}